// round 2
// baseline (speedup 1.0000x reference)
#include <cuda_runtime.h>

#define NN 8000
#define NE 24000
#define EAA 32000          // NE + NN (edges + self loops)
#define NB 256
#define ATOMD 133
#define BOND 14
#define HD 256
#define NHEADS 8
#define HH 2048            // NHEADS * HD
#define NL 5
#define NEGS 0.2f
#define LNEPS 1e-5f

// ---------------- scratch (device globals; no allocations allowed) ----------------
__device__ float g_h[NN * HD];
__device__ float g_xl[NN * HH];
__device__ float g_xr[NN * HH];
__device__ float g_loop[NN * BOND];
__device__ float g_deg[NN];
__device__ float g_score[EAA * NHEADS];
__device__ float g_smax[NN * NHEADS];
__device__ float g_ssum[NN * NHEADS];
__device__ float g_agg[NN * HD];
__device__ float g_gate[NN];
__device__ float g_gmax[NB];
__device__ float g_gsum[NB];

typedef unsigned long long u64;

__device__ __forceinline__ u64 pack_dup(float v) {
    u64 r; asm("mov.b64 %0,{%1,%1};" : "=l"(r) : "f"(v)); return r;
}
__device__ __forceinline__ u64 ffma2(u64 a, u64 b, u64 c) {
    u64 d; asm("fma.rn.f32x2 %0,%1,%2,%3;" : "=l"(d) : "l"(a), "l"(b), "l"(c)); return d;
}
__device__ __forceinline__ float2 unpack2(u64 v) {
    float2 o; asm("mov.b64 {%0,%1},%2;" : "=f"(o.x), "=f"(o.y) : "l"(v)); return o;
}

__device__ __forceinline__ void atomicMaxF(float* addr, float val) {
    unsigned int* ua = (unsigned int*)addr;
    unsigned int old = *ua;
    while (__uint_as_float(old) < val) {
        unsigned int assumed = old;
        old = atomicCAS(ua, assumed, __float_as_uint(val));
        if (old == assumed) break;
    }
}

// ---------------- init / self-loop attr ----------------
__global__ void k_init0() {
    int i = blockIdx.x * 256 + threadIdx.x;
    if (i < NN * BOND) g_loop[i] = 0.f;
    if (i < NN) g_deg[i] = 0.f;
}

__global__ void k_loop_acc(const float* __restrict__ ea, const int* __restrict__ ei) {
    int e = blockIdx.x * 256 + threadIdx.x;
    if (e >= NE) return;
    int dst = ei[NE + e];
    atomicAdd(&g_deg[dst], 1.f);
#pragma unroll
    for (int k = 0; k < BOND; k++)
        atomicAdd(&g_loop[dst * BOND + k], ea[e * BOND + k]);
}

__global__ void k_loop_fin() {
    int i = blockIdx.x * 256 + threadIdx.x;
    if (i >= NN * BOND) return;
    g_loop[i] *= (1.f / fmaxf(g_deg[i / BOND], 1.f));
}

// ---------------- atom embedding: relu(LN(x @ W + b)) ----------------
__global__ void __launch_bounds__(256) k_embed(const float* __restrict__ x, const float* __restrict__ W,
                                               const float* __restrict__ b, const float* __restrict__ g,
                                               const float* __restrict__ beta) {
    __shared__ float xs[ATOMD];
    __shared__ float red[16];
    int n = blockIdx.x, tid = threadIdx.x;
    if (tid < ATOMD) xs[tid] = x[n * ATOMD + tid];
    __syncthreads();
    float acc = b[tid];
    for (int k = 0; k < ATOMD; k++) acc = fmaf(xs[k], W[k * HD + tid], acc);
    float s = acc, q = acc * acc;
#pragma unroll
    for (int o = 16; o; o >>= 1) {
        s += __shfl_xor_sync(0xffffffffu, s, o);
        q += __shfl_xor_sync(0xffffffffu, q, o);
    }
    int w = tid >> 5, lane = tid & 31;
    if (!lane) { red[w] = s; red[8 + w] = q; }
    __syncthreads();
    if (tid == 0) {
        float ts = 0.f, tq = 0.f;
        for (int i = 0; i < 8; i++) { ts += red[i]; tq += red[8 + i]; }
        red[0] = ts; red[8] = tq;
    }
    __syncthreads();
    float mean = red[0] * (1.f / HD);
    float var = red[8] * (1.f / HD) - mean * mean;
    float v = (acc - mean) * rsqrtf(var + LNEPS) * g[tid] + beta[tid];
    g_h[n * HD + tid] = fmaxf(v, 0.f);
}

// ---------------- SGEMM: C[8000x2048] = g_h[8000x256] @ B[256x2048] ----------------
// BM=64, BN=128, BK=16, 256 threads, 4x8 per-thread tile via packed f32x2 FMAs.
__global__ void __launch_bounds__(256) k_gemm(const float* __restrict__ B, int which) {
    const float* A = g_h;
    float* C = which ? g_xr : g_xl;
    __shared__ float As[16][68];
    __shared__ float Bs[16][128];
    int tid = threadIdx.x;
    int m0 = blockIdx.y * 64;
    int n0 = blockIdx.x * 128;
    int arow = tid >> 2, acol = (tid & 3) << 2;
    int brow = tid >> 4, bcol = (tid & 15) << 3;
    int rm = (tid & 15) << 2;
    int rn = (tid >> 4) << 3;

    u64 acc[4][4];
#pragma unroll
    for (int i = 0; i < 4; i++)
#pragma unroll
        for (int j = 0; j < 4; j++) acc[i][j] = 0ull;

    const float* Aptr = A + (m0 + arow) * HD + acol;
    const float* Bptr = B + brow * HH + n0 + bcol;

    for (int k0 = 0; k0 < HD; k0 += 16) {
        float4 av = *(const float4*)(Aptr + k0);
        As[acol + 0][arow] = av.x; As[acol + 1][arow] = av.y;
        As[acol + 2][arow] = av.z; As[acol + 3][arow] = av.w;
        const float* bp = Bptr + k0 * HH;
        *(float4*)(&Bs[brow][bcol]) = *(const float4*)(bp);
        *(float4*)(&Bs[brow][bcol + 4]) = *(const float4*)(bp + 4);
        __syncthreads();
#pragma unroll
        for (int kk = 0; kk < 16; kk++) {
            float4 a4 = *(const float4*)(&As[kk][rm]);
            ulonglong2 b01 = *(const ulonglong2*)(&Bs[kk][rn]);
            ulonglong2 b23 = *(const ulonglong2*)(&Bs[kk][rn + 4]);
            float ar[4] = {a4.x, a4.y, a4.z, a4.w};
            u64 bb[4] = {b01.x, b01.y, b23.x, b23.y};
#pragma unroll
            for (int i = 0; i < 4; i++) {
                u64 aa = pack_dup(ar[i]);
#pragma unroll
                for (int j = 0; j < 4; j++) acc[i][j] = ffma2(aa, bb[j], acc[i][j]);
            }
        }
        __syncthreads();
    }
#pragma unroll
    for (int i = 0; i < 4; i++) {
        float2 p0 = unpack2(acc[i][0]), p1 = unpack2(acc[i][1]);
        float2 p2 = unpack2(acc[i][2]), p3 = unpack2(acc[i][3]);
        float* cp = C + (m0 + rm + i) * HH + n0 + rn;
        *(float4*)cp = make_float4(p0.x, p0.y, p1.x, p1.y);
        *(float4*)(cp + 4) = make_float4(p2.x, p2.y, p3.x, p3.y);
    }
}

// ---------------- per-layer init ----------------
__global__ void k_init_layer() {
    int i = blockIdx.x * 256 + threadIdx.x;
    if (i < NN * NHEADS) { g_smax[i] = __int_as_float(0xff800000); g_ssum[i] = 0.f; }
    if (i < NN * HD) g_agg[i] = 0.f;
}

// ---------------- edge score: one warp per (edge, head) ----------------
__global__ void __launch_bounds__(256) k_edge_score(const float* __restrict__ edge_attr,
                                                    const int* __restrict__ ei,
                                                    const float* __restrict__ We_l,
                                                    const float* __restrict__ att_l) {
    int gw = (blockIdx.x * 256 + threadIdx.x) >> 5;
    int lane = threadIdx.x & 31;
    if (gw >= EAA * NHEADS) return;
    int e = gw >> 3, hh = gw & 7;
    int src, dst;
    const float* earow;
    if (e < NE) { src = ei[e]; dst = ei[NE + e]; earow = edge_attr + e * BOND; }
    else { src = e - NE; dst = src; earow = g_loop + (e - NE) * BOND; }

    float ea[BOND];
#pragma unroll
    for (int k = 0; k < BOND; k++) ea[k] = earow[k];

    const float4* We4 = (const float4*)(We_l + hh * HD);
    const float4* xl4 = (const float4*)(g_xl + src * HH + hh * HD);
    const float4* xr4 = (const float4*)(g_xr + dst * HH + hh * HD);
    const float4* at4 = (const float4*)(att_l + hh * HD);

    float acc = 0.f;
#pragma unroll
    for (int it = 0; it < 2; it++) {
        int d4 = lane + it * 32;
        float4 ee = make_float4(0.f, 0.f, 0.f, 0.f);
#pragma unroll
        for (int k = 0; k < BOND; k++) {
            float4 w = We4[k * (HH / 4) + d4];
            ee.x = fmaf(ea[k], w.x, ee.x); ee.y = fmaf(ea[k], w.y, ee.y);
            ee.z = fmaf(ea[k], w.z, ee.z); ee.w = fmaf(ea[k], w.w, ee.w);
        }
        float4 a = xl4[d4], r = xr4[d4], t = at4[d4];
        float v;
        v = a.x + r.x + ee.x; v = v > 0.f ? v : NEGS * v; acc = fmaf(v, t.x, acc);
        v = a.y + r.y + ee.y; v = v > 0.f ? v : NEGS * v; acc = fmaf(v, t.y, acc);
        v = a.z + r.z + ee.z; v = v > 0.f ? v : NEGS * v; acc = fmaf(v, t.z, acc);
        v = a.w + r.w + ee.w; v = v > 0.f ? v : NEGS * v; acc = fmaf(v, t.w, acc);
    }
#pragma unroll
    for (int o = 16; o; o >>= 1) acc += __shfl_xor_sync(0xffffffffu, acc, o);
    if (!lane) {
        g_score[gw] = acc;
        atomicMaxF(&g_smax[dst * NHEADS + hh], acc);
    }
}

// ---------------- exp + segment sum ----------------
__global__ void k_expsum(const int* __restrict__ ei) {
    int i = blockIdx.x * 256 + threadIdx.x;
    if (i >= EAA * NHEADS) return;
    int e = i >> 3, hh = i & 7;
    int dst = (e < NE) ? ei[NE + e] : e - NE;
    float ex = expf(g_score[i] - g_smax[dst * NHEADS + hh]);
    g_score[i] = ex;
    atomicAdd(&g_ssum[dst * NHEADS + hh], ex);
}

// ---------------- message aggregation (head mean folded in) ----------------
__global__ void __launch_bounds__(256) k_aggregate(const int* __restrict__ ei) {
    __shared__ float al[NHEADS];
    __shared__ int sd[2];
    int e = blockIdx.x, tid = threadIdx.x;
    if (tid == 0) {
        if (e < NE) { sd[0] = ei[e]; sd[1] = ei[NE + e]; }
        else { sd[0] = sd[1] = e - NE; }
    }
    __syncthreads();
    int src = sd[0], dst = sd[1];
    if (tid < NHEADS) al[tid] = g_score[e * NHEADS + tid] / g_ssum[dst * NHEADS + tid];
    __syncthreads();
    const float* xlp = g_xl + src * HH + tid;
    float acc = 0.f;
#pragma unroll
    for (int h = 0; h < NHEADS; h++) acc = fmaf(xlp[h * HD], al[h], acc);
    atomicAdd(&g_agg[dst * HD + tid], acc * 0.125f);
}

// ---------------- residual + LayerNorm ----------------
__global__ void __launch_bounds__(256) k_ln_res(const float* __restrict__ bias,
                                                const float* __restrict__ g,
                                                const float* __restrict__ b) {
    __shared__ float red[16];
    int n = blockIdx.x, tid = threadIdx.x;
    float v = g_agg[n * HD + tid] + bias[tid] + g_h[n * HD + tid];
    float s = v, q = v * v;
#pragma unroll
    for (int o = 16; o; o >>= 1) {
        s += __shfl_xor_sync(0xffffffffu, s, o);
        q += __shfl_xor_sync(0xffffffffu, q, o);
    }
    int w = tid >> 5, lane = tid & 31;
    if (!lane) { red[w] = s; red[8 + w] = q; }
    __syncthreads();
    if (tid == 0) {
        float ts = 0.f, tq = 0.f;
        for (int i = 0; i < 8; i++) { ts += red[i]; tq += red[8 + i]; }
        red[0] = ts; red[8] = tq;
    }
    __syncthreads();
    float mean = red[0] * (1.f / HD);
    float var = red[8] * (1.f / HD) - mean * mean;
    g_h[n * HD + tid] = (v - mean) * rsqrtf(var + LNEPS) * g[tid] + b[tid];
}

// ---------------- readout ----------------
__global__ void k_init_post(float* __restrict__ out) {
    int i = blockIdx.x * 256 + threadIdx.x;
    if (i < NB) { g_gmax[i] = __int_as_float(0xff800000); g_gsum[i] = 0.f; }
    if (i < NB * HD) out[i] = 0.f;
}

__global__ void __launch_bounds__(128) k_gate(const float* __restrict__ g1W, const float* __restrict__ g1b,
                                              const float* __restrict__ g2W, const float* __restrict__ g2b,
                                              const int* __restrict__ bv) {
    __shared__ float hs[HD];
    __shared__ float rs[4];
    int n = blockIdx.x, tid = threadIdx.x;
    hs[tid] = g_h[n * HD + tid];
    hs[tid + 128] = g_h[n * HD + tid + 128];
    __syncthreads();
    float t = g1b[tid];
    for (int d = 0; d < HD; d++) t = fmaf(hs[d], g1W[d * 128 + tid], t);
    t = fmaxf(t, 0.f) * g2W[tid];
#pragma unroll
    for (int o = 16; o; o >>= 1) t += __shfl_xor_sync(0xffffffffu, t, o);
    if (!(tid & 31)) rs[tid >> 5] = t;
    __syncthreads();
    if (tid == 0) {
        float tot = rs[0] + rs[1] + rs[2] + rs[3] + g2b[0];
        g_gate[n] = tot;
        atomicMaxF(&g_gmax[bv[n]], tot);
    }
}

__global__ void k_gate_exp(const int* __restrict__ bv) {
    int i = blockIdx.x * 256 + threadIdx.x;
    if (i >= NN) return;
    int b = bv[i];
    float ge = expf(g_gate[i] - g_gmax[b]);
    g_gate[i] = ge;
    atomicAdd(&g_gsum[b], ge);
}

__global__ void __launch_bounds__(256) k_out(const int* __restrict__ bv, float* __restrict__ out) {
    int n = blockIdx.x, tid = threadIdx.x;
    int b = bv[n];
    float w = g_gate[n] / fmaxf(g_gsum[b], 1e-16f);
    atomicAdd(&out[b * HD + tid], w * g_h[n * HD + tid]);
}

// ---------------- launch ----------------
extern "C" void kernel_launch(void* const* d_in, const int* in_sizes, int n_in,
                              void* d_out, int out_size) {
    const float* x        = (const float*)d_in[0];
    const float* edge_attr= (const float*)d_in[1];
    const float* emb_W    = (const float*)d_in[2];
    const float* emb_b    = (const float*)d_in[3];
    const float* emb_g    = (const float*)d_in[4];
    const float* emb_beta = (const float*)d_in[5];
    const float* Wl       = (const float*)d_in[6];
    const float* Wr       = (const float*)d_in[7];
    const float* We       = (const float*)d_in[8];
    const float* att      = (const float*)d_in[9];
    const float* bias     = (const float*)d_in[10];
    const float* ln_g     = (const float*)d_in[11];
    const float* ln_b     = (const float*)d_in[12];
    const float* g1W      = (const float*)d_in[13];
    const float* g1b      = (const float*)d_in[14];
    const float* g2W      = (const float*)d_in[15];
    const float* g2b      = (const float*)d_in[16];
    const int*   ei       = (const int*)d_in[17];
    const int*   bv       = (const int*)d_in[18];
    float* out = (float*)d_out;

    k_init0<<<(NN * BOND + 255) / 256, 256>>>();
    k_loop_acc<<<(NE + 255) / 256, 256>>>(edge_attr, ei);
    k_loop_fin<<<(NN * BOND + 255) / 256, 256>>>();
    k_embed<<<NN, 256>>>(x, emb_W, emb_b, emb_g, emb_beta);

    for (int l = 0; l < NL; l++) {
        k_init_layer<<<(NN * HD + 255) / 256, 256>>>();
        k_gemm<<<dim3(HH / 128, NN / 64), 256>>>(Wl + l * HD * HH, 0);
        k_gemm<<<dim3(HH / 128, NN / 64), 256>>>(Wr + l * HD * HH, 1);
        k_edge_score<<<EAA * NHEADS / 8, 256>>>(edge_attr, ei, We + l * BOND * HH, att + l * NHEADS * HD);
        k_expsum<<<EAA * NHEADS / 256, 256>>>(ei);
        k_aggregate<<<EAA, 256>>>(ei);
        k_ln_res<<<NN, 256>>>(bias + l * HD, ln_g + l * HD, ln_b + l * HD);
    }

    k_init_post<<<(NB * HD + 255) / 256, 256>>>(out);
    k_gate<<<NN, 128>>>(g1W, g1b, g2W, g2b, bv);
    k_gate_exp<<<(NN + 255) / 256, 256>>>(bv);
    k_out<<<NN, 256>>>(bv, out);
}

// round 7
// speedup vs baseline: 1.5483x; 1.5483x over previous
#include <cuda_runtime.h>
#include <cuda_bf16.h>
#include <cstdint>

#define NN 8000
#define NE 24000
#define EAA 32000          // NE + NN (edges + self loops)
#define NB 256
#define ATOMD 133
#define BOND 14
#define HD 256
#define NHEADS 8
#define HH 2048            // NHEADS * HD
#define NL 5
#define NEGS 0.2f
#define LNEPS 1e-5f

// ---------------- scratch (device globals; no allocations allowed) ----------------
__device__ float g_h[NN * HD];
__device__ float g_xl[NN * HH];
__device__ float g_xr[NN * HH];
__device__ float g_loop[NN * BOND];
__device__ float g_deg[NN];
__device__ float g_score[EAA * NHEADS];
__device__ float g_smax[NN * NHEADS];
__device__ float g_ssum[NN * NHEADS];
__device__ float g_agg[NN * HD];
__device__ float g_gate[NN];
__device__ float g_gmax[NB];
__device__ float g_gsum[NB];

// bf16 split buffers for tensor-core GEMM  (all [row][k], k contiguous)
__device__ __nv_bfloat16 g_hh[NN * HD];     // h hi
__device__ __nv_bfloat16 g_hl[NN * HD];     // h lo
__device__ __nv_bfloat16 g_wlh[HH * HD];    // Wl^T hi  [n][k]
__device__ __nv_bfloat16 g_wll[HH * HD];    // Wl^T lo
__device__ __nv_bfloat16 g_wrh[HH * HD];    // Wr^T hi
__device__ __nv_bfloat16 g_wrl[HH * HD];    // Wr^T lo

__device__ __forceinline__ uint32_t smem_u32(const void* p) {
    uint32_t a;
    asm("{ .reg .u64 t; cvta.to.shared.u64 t, %1; cvt.u32.u64 %0, t; }" : "=r"(a) : "l"(p));
    return a;
}

__device__ __forceinline__ void atomicMaxF(float* addr, float val) {
    unsigned int* ua = (unsigned int*)addr;
    unsigned int old = *ua;
    while (__uint_as_float(old) < val) {
        unsigned int assumed = old;
        old = atomicCAS(ua, assumed, __float_as_uint(val));
        if (old == assumed) break;
    }
}

// ---------------- init / self-loop attr ----------------
__global__ void k_init0() {
    int i = blockIdx.x * 256 + threadIdx.x;
    if (i < NN * BOND) g_loop[i] = 0.f;
    if (i < NN) g_deg[i] = 0.f;
}

__global__ void k_loop_acc(const float* __restrict__ ea, const int* __restrict__ ei) {
    int e = blockIdx.x * 256 + threadIdx.x;
    if (e >= NE) return;
    int dst = ei[NE + e];
    atomicAdd(&g_deg[dst], 1.f);
#pragma unroll
    for (int k = 0; k < BOND; k++)
        atomicAdd(&g_loop[dst * BOND + k], ea[e * BOND + k]);
}

__global__ void k_loop_fin() {
    int i = blockIdx.x * 256 + threadIdx.x;
    if (i >= NN * BOND) return;
    g_loop[i] *= (1.f / fmaxf(g_deg[i / BOND], 1.f));
}

// ---------------- atom embedding: relu(LN(x @ W + b)) ----------------
__global__ void __launch_bounds__(256) k_embed(const float* __restrict__ x, const float* __restrict__ W,
                                               const float* __restrict__ b, const float* __restrict__ g,
                                               const float* __restrict__ beta) {
    __shared__ float xs[ATOMD];
    __shared__ float red[16];
    int n = blockIdx.x, tid = threadIdx.x;
    if (tid < ATOMD) xs[tid] = x[n * ATOMD + tid];
    __syncthreads();
    float acc = b[tid];
    for (int k = 0; k < ATOMD; k++) acc = fmaf(xs[k], W[k * HD + tid], acc);
    float s = acc, q = acc * acc;
#pragma unroll
    for (int o = 16; o; o >>= 1) {
        s += __shfl_xor_sync(0xffffffffu, s, o);
        q += __shfl_xor_sync(0xffffffffu, q, o);
    }
    int w = tid >> 5, lane = tid & 31;
    if (!lane) { red[w] = s; red[8 + w] = q; }
    __syncthreads();
    if (tid == 0) {
        float ts = 0.f, tq = 0.f;
        for (int i = 0; i < 8; i++) { ts += red[i]; tq += red[8 + i]; }
        red[0] = ts; red[8] = tq;
    }
    __syncthreads();
    float mean = red[0] * (1.f / HD);
    float var = red[8] * (1.f / HD) - mean * mean;
    float v = (acc - mean) * rsqrtf(var + LNEPS) * g[tid] + beta[tid];
    g_h[n * HD + tid] = fmaxf(v, 0.f);
}

// ---------------- bf16 hi/lo split of h ----------------
__global__ void k_h_split() {
    int i = blockIdx.x * 256 + threadIdx.x;   // NN*HD exact
    float v = g_h[i];
    __nv_bfloat16 hi = __float2bfloat16(v);
    g_hh[i] = hi;
    g_hl[i] = __float2bfloat16(v - __bfloat162float(hi));
}

// ---------------- W transpose + bf16 split (tiled, coalesced both sides) ----------
__global__ void __launch_bounds__(256) k_w_split(const float* __restrict__ Wl_l,
                                                 const float* __restrict__ Wr_l) {
    __shared__ float tl[32][33];
    __shared__ float tr[32][33];
    int nt = blockIdx.x;             // HH/32 = 64
    int kt = blockIdx.y;             // HD/32 = 8
    int tx = threadIdx.x & 31, ty = threadIdx.x >> 5;   // 8 rows per pass
#pragma unroll
    for (int p = 0; p < 4; p++) {
        int k = kt * 32 + p * 8 + ty;
        tl[p * 8 + ty][tx] = Wl_l[(size_t)k * HH + nt * 32 + tx];
        tr[p * 8 + ty][tx] = Wr_l[(size_t)k * HH + nt * 32 + tx];
    }
    __syncthreads();
#pragma unroll
    for (int p = 0; p < 4; p++) {
        int n = nt * 32 + p * 8 + ty;
        int k = kt * 32 + tx;
        size_t o = (size_t)n * HD + k;
        float a = tl[tx][p * 8 + ty];
        float b = tr[tx][p * 8 + ty];
        __nv_bfloat16 ah = __float2bfloat16(a);
        __nv_bfloat16 bh = __float2bfloat16(b);
        g_wlh[o] = ah; g_wll[o] = __float2bfloat16(a - __bfloat162float(ah));
        g_wrh[o] = bh; g_wrl[o] = __float2bfloat16(b - __bfloat162float(bh));
    }
}

// ============================ HMMA GEMM ============================
// C[NN x HH] = A[NN x 256] @ B^T  with A,B given as bf16 hi/lo splits, [row][k].
// Block tile 128x128, BK=32, 8 warps (2 m x 4 n), warp tile 64x32.
// 3-term compensated product: Ah*Bh + Ah*Bl + Al*Bh, fp32 accum.
#define TILEB 8192            // 128 rows * 64B (32 bf16)
#define STAGEB (4 * TILEB)    // Ah, Al, Bh, Bl
#define GEMM_SMEM (2 * STAGEB)

__device__ __forceinline__ void cp16(uint32_t dst, const void* src, unsigned sz) {
    asm volatile("cp.async.cg.shared.global [%0], [%1], 16, %2;"
                 :: "r"(dst), "l"(src), "r"(sz) : "memory");
}

// load one 128x32 bf16 tile (k-chunk kc of a [row][256] matrix) with XOR swizzle
__device__ __forceinline__ void load_tile_cp(uint32_t sdst, const __nv_bfloat16* __restrict__ g,
                                             int row0, int kc, int tid, int maxrow) {
#pragma unroll
    for (int rep = 0; rep < 2; rep++) {
        int idx = tid + rep * 256;          // 0..511
        int r = idx >> 2, c = idx & 3;      // row 0..127, 16B chunk 0..3
        int gr = row0 + r;
        unsigned sz = (gr < maxrow) ? 16u : 0u;
        if (gr >= maxrow) gr = 0;
        const char* src = (const char*)g + (size_t)gr * 512 + kc * 64 + c * 16;
        uint32_t dst = sdst + r * 64 + ((c ^ ((r >> 1) & 3)) * 16);
        cp16(dst, src, sz);
    }
}

__device__ __forceinline__ uint32_t ldm_addr(uint32_t tb, int row0, int kk, int lane) {
    int r = row0 + ((lane >> 3) & 1) * 8 + (lane & 7);
    int c = 2 * kk + (lane >> 4);
    return tb + r * 64 + ((c ^ ((r >> 1) & 3)) * 16);
}

__device__ __forceinline__ void ldm4(uint32_t* r, uint32_t addr) {
    asm volatile("ldmatrix.sync.aligned.m8n8.x4.shared.b16 {%0,%1,%2,%3}, [%4];"
                 : "=r"(r[0]), "=r"(r[1]), "=r"(r[2]), "=r"(r[3]) : "r"(addr));
}

__device__ __forceinline__ void mma16816(float* d, const uint32_t* a, uint32_t b0, uint32_t b1) {
    asm volatile("mma.sync.aligned.m16n8k16.row.col.f32.bf16.bf16.f32 "
                 "{%0,%1,%2,%3}, {%4,%5,%6,%7}, {%8,%9}, {%0,%1,%2,%3};"
                 : "+f"(d[0]), "+f"(d[1]), "+f"(d[2]), "+f"(d[3])
                 : "r"(a[0]), "r"(a[1]), "r"(a[2]), "r"(a[3]), "r"(b0), "r"(b1));
}

// which==0: C=g_xl, B=g_wlh/g_wll.  which==1: C=g_xr, B=g_wrh/g_wrl.
// (device globals MUST be resolved in device code, not passed from host!)
__global__ void __launch_bounds__(256, 1) k_gemm_mma(int which) {
    const __nv_bfloat16* __restrict__ Bhp = which ? g_wrh : g_wlh;
    const __nv_bfloat16* __restrict__ Blp = which ? g_wrl : g_wll;
    float* __restrict__ C = which ? g_xr : g_xl;

    extern __shared__ char smem[];
    uint32_t sb = smem_u32(smem);
    int tid = threadIdx.x, lane = tid & 31, wid = tid >> 5;
    int m0 = blockIdx.y * 128, n0 = blockIdx.x * 128;
    int wm = (wid & 1) * 64, wn = (wid >> 1) * 32;

    float acc[4][4][4];
#pragma unroll
    for (int i = 0; i < 4; i++)
#pragma unroll
        for (int j = 0; j < 4; j++)
#pragma unroll
            for (int q = 0; q < 4; q++) acc[i][j][q] = 0.f;

    // prologue: stage 0
    load_tile_cp(sb + 0 * TILEB, g_hh, m0, 0, tid, NN);
    load_tile_cp(sb + 1 * TILEB, g_hl, m0, 0, tid, NN);
    load_tile_cp(sb + 2 * TILEB, Bhp, n0, 0, tid, HH);
    load_tile_cp(sb + 3 * TILEB, Blp, n0, 0, tid, HH);
    asm volatile("cp.async.commit_group;" ::: "memory");

#pragma unroll 1
    for (int kc = 0; kc < 8; kc++) {
        uint32_t cur = sb + (kc & 1) * STAGEB;
        if (kc < 7) {
            uint32_t nxt = sb + ((kc + 1) & 1) * STAGEB;
            load_tile_cp(nxt + 0 * TILEB, g_hh, m0, kc + 1, tid, NN);
            load_tile_cp(nxt + 1 * TILEB, g_hl, m0, kc + 1, tid, NN);
            load_tile_cp(nxt + 2 * TILEB, Bhp, n0, kc + 1, tid, HH);
            load_tile_cp(nxt + 3 * TILEB, Blp, n0, kc + 1, tid, HH);
            asm volatile("cp.async.commit_group;" ::: "memory");
            asm volatile("cp.async.wait_group 1;" ::: "memory");
        } else {
            asm volatile("cp.async.wait_group 0;" ::: "memory");
        }
        __syncthreads();
#pragma unroll
        for (int kk = 0; kk < 2; kk++) {
            uint32_t ah[4][4], al[4][4], bh[2][4], bl[2][4];
#pragma unroll
            for (int mi = 0; mi < 4; mi++) ldm4(ah[mi], ldm_addr(cur + 0 * TILEB, wm + mi * 16, kk, lane));
#pragma unroll
            for (int mi = 0; mi < 4; mi++) ldm4(al[mi], ldm_addr(cur + 1 * TILEB, wm + mi * 16, kk, lane));
#pragma unroll
            for (int bi = 0; bi < 2; bi++) ldm4(bh[bi], ldm_addr(cur + 2 * TILEB, wn + bi * 16, kk, lane));
#pragma unroll
            for (int bi = 0; bi < 2; bi++) ldm4(bl[bi], ldm_addr(cur + 3 * TILEB, wn + bi * 16, kk, lane));
#pragma unroll
            for (int mi = 0; mi < 4; mi++)
#pragma unroll
                for (int j = 0; j < 4; j++) {
                    int bi = j >> 1, s = j & 1;
                    mma16816(acc[mi][j], ah[mi], bh[bi][s], bh[bi][s + 2]);
                    mma16816(acc[mi][j], ah[mi], bl[bi][s], bl[bi][s + 2]);
                    mma16816(acc[mi][j], al[mi], bh[bi][s], bh[bi][s + 2]);
                }
        }
        __syncthreads();
    }

    // epilogue
#pragma unroll
    for (int mi = 0; mi < 4; mi++) {
        int r = m0 + wm + mi * 16 + (lane >> 2);
#pragma unroll
        for (int j = 0; j < 4; j++) {
            int cc = n0 + wn + j * 8 + (lane & 3) * 2;
            if (r < NN)
                *(float2*)(C + (size_t)r * HH + cc) = make_float2(acc[mi][j][0], acc[mi][j][1]);
            if (r + 8 < NN)
                *(float2*)(C + (size_t)(r + 8) * HH + cc) = make_float2(acc[mi][j][2], acc[mi][j][3]);
        }
    }
}

// ---------------- per-layer init ----------------
__global__ void k_init_layer() {
    int i = blockIdx.x * 256 + threadIdx.x;
    if (i < NN * NHEADS) { g_smax[i] = __int_as_float(0xff800000); g_ssum[i] = 0.f; }
    if (i < NN * HD) g_agg[i] = 0.f;
}

// ---------------- edge score: one warp per (edge, head) ----------------
__global__ void __launch_bounds__(256) k_edge_score(const float* __restrict__ edge_attr,
                                                    const int* __restrict__ ei,
                                                    const float* __restrict__ We_l,
                                                    const float* __restrict__ att_l) {
    int gw = (blockIdx.x * 256 + threadIdx.x) >> 5;
    int lane = threadIdx.x & 31;
    if (gw >= EAA * NHEADS) return;
    int e = gw >> 3, hh = gw & 7;
    int src, dst;
    const float* earow;
    if (e < NE) { src = ei[e]; dst = ei[NE + e]; earow = edge_attr + e * BOND; }
    else { src = e - NE; dst = src; earow = g_loop + (e - NE) * BOND; }

    float ea[BOND];
#pragma unroll
    for (int k = 0; k < BOND; k++) ea[k] = earow[k];

    const float4* We4 = (const float4*)(We_l + hh * HD);
    const float4* xl4 = (const float4*)(g_xl + (size_t)src * HH + hh * HD);
    const float4* xr4 = (const float4*)(g_xr + (size_t)dst * HH + hh * HD);
    const float4* at4 = (const float4*)(att_l + hh * HD);

    float acc = 0.f;
#pragma unroll
    for (int it = 0; it < 2; it++) {
        int d4 = lane + it * 32;
        float4 ee = make_float4(0.f, 0.f, 0.f, 0.f);
#pragma unroll
        for (int k = 0; k < BOND; k++) {
            float4 w = We4[k * (HH / 4) + d4];
            ee.x = fmaf(ea[k], w.x, ee.x); ee.y = fmaf(ea[k], w.y, ee.y);
            ee.z = fmaf(ea[k], w.z, ee.z); ee.w = fmaf(ea[k], w.w, ee.w);
        }
        float4 a = xl4[d4], r = xr4[d4], t = at4[d4];
        float v;
        v = a.x + r.x + ee.x; v = v > 0.f ? v : NEGS * v; acc = fmaf(v, t.x, acc);
        v = a.y + r.y + ee.y; v = v > 0.f ? v : NEGS * v; acc = fmaf(v, t.y, acc);
        v = a.z + r.z + ee.z; v = v > 0.f ? v : NEGS * v; acc = fmaf(v, t.z, acc);
        v = a.w + r.w + ee.w; v = v > 0.f ? v : NEGS * v; acc = fmaf(v, t.w, acc);
    }
#pragma unroll
    for (int o = 16; o; o >>= 1) acc += __shfl_xor_sync(0xffffffffu, acc, o);
    if (!lane) {
        g_score[gw] = acc;
        atomicMaxF(&g_smax[dst * NHEADS + hh], acc);
    }
}

// ---------------- exp + segment sum ----------------
__global__ void k_expsum(const int* __restrict__ ei) {
    int i = blockIdx.x * 256 + threadIdx.x;
    if (i >= EAA * NHEADS) return;
    int e = i >> 3, hh = i & 7;
    int dst = (e < NE) ? ei[NE + e] : e - NE;
    float ex = expf(g_score[i] - g_smax[dst * NHEADS + hh]);
    g_score[i] = ex;
    atomicAdd(&g_ssum[dst * NHEADS + hh], ex);
}

// ---------------- message aggregation (head mean folded in) ----------------
__global__ void __launch_bounds__(256) k_aggregate(const int* __restrict__ ei) {
    __shared__ float al[NHEADS];
    __shared__ int sd[2];
    int e = blockIdx.x, tid = threadIdx.x;
    if (tid == 0) {
        if (e < NE) { sd[0] = ei[e]; sd[1] = ei[NE + e]; }
        else { sd[0] = sd[1] = e - NE; }
    }
    __syncthreads();
    int src = sd[0], dst = sd[1];
    if (tid < NHEADS) al[tid] = g_score[e * NHEADS + tid] / g_ssum[dst * NHEADS + tid];
    __syncthreads();
    const float* xlp = g_xl + (size_t)src * HH + tid;
    float acc = 0.f;
#pragma unroll
    for (int h = 0; h < NHEADS; h++) acc = fmaf(xlp[h * HD], al[h], acc);
    atomicAdd(&g_agg[dst * HD + tid], acc * 0.125f);
}

// ---------------- residual + LayerNorm ----------------
__global__ void __launch_bounds__(256) k_ln_res(const float* __restrict__ bias,
                                                const float* __restrict__ g,
                                                const float* __restrict__ b) {
    __shared__ float red[16];
    int n = blockIdx.x, tid = threadIdx.x;
    float v = g_agg[n * HD + tid] + bias[tid] + g_h[n * HD + tid];
    float s = v, q = v * v;
#pragma unroll
    for (int o = 16; o; o >>= 1) {
        s += __shfl_xor_sync(0xffffffffu, s, o);
        q += __shfl_xor_sync(0xffffffffu, q, o);
    }
    int w = tid >> 5, lane = tid & 31;
    if (!lane) { red[w] = s; red[8 + w] = q; }
    __syncthreads();
    if (tid == 0) {
        float ts = 0.f, tq = 0.f;
        for (int i = 0; i < 8; i++) { ts += red[i]; tq += red[8 + i]; }
        red[0] = ts; red[8] = tq;
    }
    __syncthreads();
    float mean = red[0] * (1.f / HD);
    float var = red[8] * (1.f / HD) - mean * mean;
    g_h[n * HD + tid] = (v - mean) * rsqrtf(var + LNEPS) * g[tid] + b[tid];
}

// ---------------- readout ----------------
__global__ void k_init_post(float* __restrict__ out) {
    int i = blockIdx.x * 256 + threadIdx.x;
    if (i < NB) { g_gmax[i] = __int_as_float(0xff800000); g_gsum[i] = 0.f; }
    if (i < NB * HD) out[i] = 0.f;
}

__global__ void __launch_bounds__(128) k_gate(const float* __restrict__ g1W, const float* __restrict__ g1b,
                                              const float* __restrict__ g2W, const float* __restrict__ g2b,
                                              const int* __restrict__ bv) {
    __shared__ float hs[HD];
    __shared__ float rs[4];
    int n = blockIdx.x, tid = threadIdx.x;
    hs[tid] = g_h[n * HD + tid];
    hs[tid + 128] = g_h[n * HD + tid + 128];
    __syncthreads();
    float t = g1b[tid];
    for (int d = 0; d < HD; d++) t = fmaf(hs[d], g1W[d * 128 + tid], t);
    t = fmaxf(t, 0.f) * g2W[tid];
#pragma unroll
    for (int o = 16; o; o >>= 1) t += __shfl_xor_sync(0xffffffffu, t, o);
    if (!(tid & 31)) rs[tid >> 5] = t;
    __syncthreads();
    if (tid == 0) {
        float tot = rs[0] + rs[1] + rs[2] + rs[3] + g2b[0];
        g_gate[n] = tot;
        atomicMaxF(&g_gmax[bv[n]], tot);
    }
}

__global__ void k_gate_exp(const int* __restrict__ bv) {
    int i = blockIdx.x * 256 + threadIdx.x;
    if (i >= NN) return;
    int b = bv[i];
    float ge = expf(g_gate[i] - g_gmax[b]);
    g_gate[i] = ge;
    atomicAdd(&g_gsum[b], ge);
}

__global__ void __launch_bounds__(256) k_out(const int* __restrict__ bv, float* __restrict__ out) {
    int n = blockIdx.x, tid = threadIdx.x;
    int b = bv[n];
    float w = g_gate[n] / fmaxf(g_gsum[b], 1e-16f);
    atomicAdd(&out[b * HD + tid], w * g_h[n * HD + tid]);
}

// ---------------- launch ----------------
extern "C" void kernel_launch(void* const* d_in, const int* in_sizes, int n_in,
                              void* d_out, int out_size) {
    const float* x        = (const float*)d_in[0];
    const float* edge_attr= (const float*)d_in[1];
    const float* emb_W    = (const float*)d_in[2];
    const float* emb_b    = (const float*)d_in[3];
    const float* emb_g    = (const float*)d_in[4];
    const float* emb_beta = (const float*)d_in[5];
    const float* Wl       = (const float*)d_in[6];
    const float* Wr       = (const float*)d_in[7];
    const float* We       = (const float*)d_in[8];
    const float* att      = (const float*)d_in[9];
    const float* bias     = (const float*)d_in[10];
    const float* ln_g     = (const float*)d_in[11];
    const float* ln_b     = (const float*)d_in[12];
    const float* g1W      = (const float*)d_in[13];
    const float* g1b      = (const float*)d_in[14];
    const float* g2W      = (const float*)d_in[15];
    const float* g2b      = (const float*)d_in[16];
    const int*   ei       = (const int*)d_in[17];
    const int*   bv       = (const int*)d_in[18];
    float* out = (float*)d_out;

    cudaFuncSetAttribute(k_gemm_mma, cudaFuncAttributeMaxDynamicSharedMemorySize, GEMM_SMEM);

    k_init0<<<(NN * BOND + 255) / 256, 256>>>();
    k_loop_acc<<<(NE + 255) / 256, 256>>>(edge_attr, ei);
    k_loop_fin<<<(NN * BOND + 255) / 256, 256>>>();
    k_embed<<<NN, 256>>>(x, emb_W, emb_b, emb_g, emb_beta);

    dim3 ggrid(HH / 128, (NN + 127) / 128);
    for (int l = 0; l < NL; l++) {
        k_h_split<<<NN, 256>>>();
        k_w_split<<<dim3(HH / 32, HD / 32), 256>>>(Wl + (size_t)l * HD * HH, Wr + (size_t)l * HD * HH);
        k_init_layer<<<(NN * HD + 255) / 256, 256>>>();
        k_gemm_mma<<<ggrid, 256, GEMM_SMEM>>>(0);
        k_gemm_mma<<<ggrid, 256, GEMM_SMEM>>>(1);
        k_edge_score<<<EAA * NHEADS / 8, 256>>>(edge_attr, ei, We + (size_t)l * BOND * HH,
                                                att + (size_t)l * NHEADS * HD);
        k_expsum<<<EAA * NHEADS / 256, 256>>>(ei);
        k_aggregate<<<EAA, 256>>>(ei);
        k_ln_res<<<NN, 256>>>(bias + l * HD, ln_g + l * HD, ln_b + l * HD);
    }

    k_init_post<<<(NB * HD + 255) / 256, 256>>>(out);
    k_gate<<<NN, 128>>>(g1W, g1b, g2W, g2b, bv);
    k_gate_exp<<<(NN + 255) / 256, 256>>>(bv);
    k_out<<<NN, 256>>>(bv, out);
}

// round 10
// speedup vs baseline: 1.8095x; 1.1686x over previous
#include <cuda_runtime.h>
#include <cuda_bf16.h>
#include <cstdint>

#define NN 8000
#define NE 24000
#define EAA 32000          // NE + NN (edges + self loops)
#define NB 256
#define ATOMD 133
#define BOND 14
#define HD 256
#define NHEADS 8
#define HH 2048            // NHEADS * HD
#define NL 5
#define NEGS 0.2f
#define LNEPS 1e-5f

// ---------------- scratch (device globals; no allocations allowed) ----------------
__device__ float g_h[NN * HD];
__device__ float g_xl[NN * HH];
__device__ float g_xr[NN * HH];
__device__ float g_loop[NN * BOND];
__device__ float g_deg[NN];
__device__ float g_gate[NN];
__device__ float g_gmax[NB];
__device__ float g_gsum[NB];

// CSR over destination nodes (edges + self-loops)
__device__ int g_csr_ptr[NN + 1];
__device__ int g_deg_i[NN];        // counter, then cursor
__device__ int g_csr_eid[EAA];

// bf16 split buffers for tensor-core GEMM  (all [row][k], k contiguous)
__device__ __nv_bfloat16 g_hh[NN * HD];     // h hi
__device__ __nv_bfloat16 g_hl[NN * HD];     // h lo
__device__ __nv_bfloat16 g_wlh[HH * HD];    // Wl^T hi  [n][k]
__device__ __nv_bfloat16 g_wll[HH * HD];    // Wl^T lo
__device__ __nv_bfloat16 g_wrh[HH * HD];    // Wr^T hi
__device__ __nv_bfloat16 g_wrl[HH * HD];    // Wr^T lo

__device__ __forceinline__ uint32_t smem_u32(const void* p) {
    uint32_t a;
    asm("{ .reg .u64 t; cvta.to.shared.u64 t, %1; cvt.u32.u64 %0, t; }" : "=r"(a) : "l"(p));
    return a;
}

__device__ __forceinline__ void atomicMaxF(float* addr, float val) {
    unsigned int* ua = (unsigned int*)addr;
    unsigned int old = *ua;
    while (__uint_as_float(old) < val) {
        unsigned int assumed = old;
        old = atomicCAS(ua, assumed, __float_as_uint(val));
        if (old == assumed) break;
    }
}

// ---------------- init / self-loop attr ----------------
__global__ void k_init0() {
    int i = blockIdx.x * 256 + threadIdx.x;
    if (i < NN * BOND) g_loop[i] = 0.f;
    if (i < NN) { g_deg[i] = 0.f; g_deg_i[i] = 0; }
}

__global__ void k_loop_acc(const float* __restrict__ ea, const int* __restrict__ ei) {
    int e = blockIdx.x * 256 + threadIdx.x;
    if (e >= NE) return;
    int dst = ei[NE + e];
    atomicAdd(&g_deg[dst], 1.f);
#pragma unroll
    for (int k = 0; k < BOND; k++)
        atomicAdd(&g_loop[dst * BOND + k], ea[e * BOND + k]);
}

__global__ void k_loop_fin() {
    int i = blockIdx.x * 256 + threadIdx.x;
    if (i >= NN * BOND) return;
    g_loop[i] *= (1.f / fmaxf(g_deg[i / BOND], 1.f));
}

// ---------------- CSR build ----------------
__global__ void k_csr_count(const int* __restrict__ ei) {
    int e = blockIdx.x * 256 + threadIdx.x;
    if (e >= EAA) return;
    int dst = (e < NE) ? ei[NE + e] : e - NE;
    atomicAdd(&g_deg_i[dst], 1);
}

__global__ void __launch_bounds__(1024) k_csr_scan() {
    __shared__ int wsum[32];
    int tid = threadIdx.x, lane = tid & 31, w = tid >> 5;
    int vals[8];
    int loc = 0;
#pragma unroll
    for (int j = 0; j < 8; j++) {
        int idx = tid * 8 + j;
        int v = (idx < NN) ? g_deg_i[idx] : 0;
        vals[j] = loc;
        loc += v;
    }
    int x = loc;
#pragma unroll
    for (int o = 1; o < 32; o <<= 1) {
        int y = __shfl_up_sync(0xffffffffu, x, o);
        if (lane >= o) x += y;
    }
    if (lane == 31) wsum[w] = x;
    __syncthreads();
    if (w == 0) {
        int y = wsum[lane];
#pragma unroll
        for (int o = 1; o < 32; o <<= 1) {
            int z = __shfl_up_sync(0xffffffffu, y, o);
            if (lane >= o) y += z;
        }
        wsum[lane] = y;
    }
    __syncthreads();
    int base = (w ? wsum[w - 1] : 0) + x - loc;   // exclusive offset of this thread
#pragma unroll
    for (int j = 0; j < 8; j++) {
        int idx = tid * 8 + j;
        if (idx < NN) { g_csr_ptr[idx] = base + vals[j]; g_deg_i[idx] = 0; }
    }
    if (tid == 0) g_csr_ptr[NN] = EAA;
}

__global__ void k_csr_fill(const int* __restrict__ ei) {
    int e = blockIdx.x * 256 + threadIdx.x;
    if (e >= EAA) return;
    int dst = (e < NE) ? ei[NE + e] : e - NE;
    int pos = atomicAdd(&g_deg_i[dst], 1);
    g_csr_eid[g_csr_ptr[dst] + pos] = e;
}

// ---------------- atom embedding: relu(LN(x @ W + b)) + bf16 split ----------------
__global__ void __launch_bounds__(256) k_embed(const float* __restrict__ x, const float* __restrict__ W,
                                               const float* __restrict__ b, const float* __restrict__ g,
                                               const float* __restrict__ beta) {
    __shared__ float xs[ATOMD];
    __shared__ float red[16];
    int n = blockIdx.x, tid = threadIdx.x;
    if (tid < ATOMD) xs[tid] = x[n * ATOMD + tid];
    __syncthreads();
    float acc = b[tid];
    for (int k = 0; k < ATOMD; k++) acc = fmaf(xs[k], W[k * HD + tid], acc);
    float s = acc, q = acc * acc;
#pragma unroll
    for (int o = 16; o; o >>= 1) {
        s += __shfl_xor_sync(0xffffffffu, s, o);
        q += __shfl_xor_sync(0xffffffffu, q, o);
    }
    int w = tid >> 5, lane = tid & 31;
    if (!lane) { red[w] = s; red[8 + w] = q; }
    __syncthreads();
    if (tid == 0) {
        float ts = 0.f, tq = 0.f;
        for (int i = 0; i < 8; i++) { ts += red[i]; tq += red[8 + i]; }
        red[0] = ts; red[8] = tq;
    }
    __syncthreads();
    float mean = red[0] * (1.f / HD);
    float var = red[8] * (1.f / HD) - mean * mean;
    float v = (acc - mean) * rsqrtf(var + LNEPS) * g[tid] + beta[tid];
    float hv = fmaxf(v, 0.f);
    int o = n * HD + tid;
    g_h[o] = hv;
    __nv_bfloat16 hi = __float2bfloat16(hv);
    g_hh[o] = hi;
    g_hl[o] = __float2bfloat16(hv - __bfloat162float(hi));
}

// ---------------- W transpose + bf16 split (tiled, coalesced both sides) ----------
__global__ void __launch_bounds__(256) k_w_split(const float* __restrict__ Wl_l,
                                                 const float* __restrict__ Wr_l) {
    __shared__ float tl[32][33];
    __shared__ float tr[32][33];
    int nt = blockIdx.x;             // HH/32 = 64
    int kt = blockIdx.y;             // HD/32 = 8
    int tx = threadIdx.x & 31, ty = threadIdx.x >> 5;   // 8 rows per pass
#pragma unroll
    for (int p = 0; p < 4; p++) {
        int k = kt * 32 + p * 8 + ty;
        tl[p * 8 + ty][tx] = Wl_l[(size_t)k * HH + nt * 32 + tx];
        tr[p * 8 + ty][tx] = Wr_l[(size_t)k * HH + nt * 32 + tx];
    }
    __syncthreads();
#pragma unroll
    for (int p = 0; p < 4; p++) {
        int n = nt * 32 + p * 8 + ty;
        int k = kt * 32 + tx;
        size_t o = (size_t)n * HD + k;
        float a = tl[tx][p * 8 + ty];
        float b = tr[tx][p * 8 + ty];
        __nv_bfloat16 ah = __float2bfloat16(a);
        __nv_bfloat16 bh = __float2bfloat16(b);
        g_wlh[o] = ah; g_wll[o] = __float2bfloat16(a - __bfloat162float(ah));
        g_wrh[o] = bh; g_wrl[o] = __float2bfloat16(b - __bfloat162float(bh));
    }
}

// ============================ HMMA GEMM ============================
#define TILEB 8192            // 128 rows * 64B (32 bf16)
#define STAGEB (4 * TILEB)    // Ah, Al, Bh, Bl
#define GEMM_SMEM (2 * STAGEB)

__device__ __forceinline__ void cp16(uint32_t dst, const void* src, unsigned sz) {
    asm volatile("cp.async.cg.shared.global [%0], [%1], 16, %2;"
                 :: "r"(dst), "l"(src), "r"(sz) : "memory");
}

__device__ __forceinline__ void load_tile_cp(uint32_t sdst, const __nv_bfloat16* __restrict__ g,
                                             int row0, int kc, int tid, int maxrow) {
#pragma unroll
    for (int rep = 0; rep < 2; rep++) {
        int idx = tid + rep * 256;          // 0..511
        int r = idx >> 2, c = idx & 3;      // row 0..127, 16B chunk 0..3
        int gr = row0 + r;
        unsigned sz = (gr < maxrow) ? 16u : 0u;
        if (gr >= maxrow) gr = 0;
        const char* src = (const char*)g + (size_t)gr * 512 + kc * 64 + c * 16;
        uint32_t dst = sdst + r * 64 + ((c ^ ((r >> 1) & 3)) * 16);
        cp16(dst, src, sz);
    }
}

__device__ __forceinline__ uint32_t ldm_addr(uint32_t tb, int row0, int kk, int lane) {
    int r = row0 + ((lane >> 3) & 1) * 8 + (lane & 7);
    int c = 2 * kk + (lane >> 4);
    return tb + r * 64 + ((c ^ ((r >> 1) & 3)) * 16);
}

__device__ __forceinline__ void ldm4(uint32_t* r, uint32_t addr) {
    asm volatile("ldmatrix.sync.aligned.m8n8.x4.shared.b16 {%0,%1,%2,%3}, [%4];"
                 : "=r"(r[0]), "=r"(r[1]), "=r"(r[2]), "=r"(r[3]) : "r"(addr));
}

__device__ __forceinline__ void mma16816(float* d, const uint32_t* a, uint32_t b0, uint32_t b1) {
    asm volatile("mma.sync.aligned.m16n8k16.row.col.f32.bf16.bf16.f32 "
                 "{%0,%1,%2,%3}, {%4,%5,%6,%7}, {%8,%9}, {%0,%1,%2,%3};"
                 : "+f"(d[0]), "+f"(d[1]), "+f"(d[2]), "+f"(d[3])
                 : "r"(a[0]), "r"(a[1]), "r"(a[2]), "r"(a[3]), "r"(b0), "r"(b1));
}

// blockIdx.z==0: C=g_xl, B=g_wlh/g_wll.  z==1: C=g_xr, B=g_wrh/g_wrl.
__global__ void __launch_bounds__(256, 1) k_gemm_mma() {
    int which = blockIdx.z;
    const __nv_bfloat16* __restrict__ Bhp = which ? g_wrh : g_wlh;
    const __nv_bfloat16* __restrict__ Blp = which ? g_wrl : g_wll;
    float* __restrict__ C = which ? g_xr : g_xl;

    extern __shared__ char smem[];
    uint32_t sb = smem_u32(smem);
    int tid = threadIdx.x, lane = tid & 31, wid = tid >> 5;
    int m0 = blockIdx.y * 128, n0 = blockIdx.x * 128;
    int wm = (wid & 1) * 64, wn = (wid >> 1) * 32;

    float acc[4][4][4];
#pragma unroll
    for (int i = 0; i < 4; i++)
#pragma unroll
        for (int j = 0; j < 4; j++)
#pragma unroll
            for (int q = 0; q < 4; q++) acc[i][j][q] = 0.f;

    load_tile_cp(sb + 0 * TILEB, g_hh, m0, 0, tid, NN);
    load_tile_cp(sb + 1 * TILEB, g_hl, m0, 0, tid, NN);
    load_tile_cp(sb + 2 * TILEB, Bhp, n0, 0, tid, HH);
    load_tile_cp(sb + 3 * TILEB, Blp, n0, 0, tid, HH);
    asm volatile("cp.async.commit_group;" ::: "memory");

#pragma unroll 1
    for (int kc = 0; kc < 8; kc++) {
        uint32_t cur = sb + (kc & 1) * STAGEB;
        if (kc < 7) {
            uint32_t nxt = sb + ((kc + 1) & 1) * STAGEB;
            load_tile_cp(nxt + 0 * TILEB, g_hh, m0, kc + 1, tid, NN);
            load_tile_cp(nxt + 1 * TILEB, g_hl, m0, kc + 1, tid, NN);
            load_tile_cp(nxt + 2 * TILEB, Bhp, n0, kc + 1, tid, HH);
            load_tile_cp(nxt + 3 * TILEB, Blp, n0, kc + 1, tid, HH);
            asm volatile("cp.async.commit_group;" ::: "memory");
            asm volatile("cp.async.wait_group 1;" ::: "memory");
        } else {
            asm volatile("cp.async.wait_group 0;" ::: "memory");
        }
        __syncthreads();
#pragma unroll
        for (int kk = 0; kk < 2; kk++) {
            uint32_t ah[4][4], al[4][4], bh[2][4], bl[2][4];
#pragma unroll
            for (int mi = 0; mi < 4; mi++) ldm4(ah[mi], ldm_addr(cur + 0 * TILEB, wm + mi * 16, kk, lane));
#pragma unroll
            for (int mi = 0; mi < 4; mi++) ldm4(al[mi], ldm_addr(cur + 1 * TILEB, wm + mi * 16, kk, lane));
#pragma unroll
            for (int bi = 0; bi < 2; bi++) ldm4(bh[bi], ldm_addr(cur + 2 * TILEB, wn + bi * 16, kk, lane));
#pragma unroll
            for (int bi = 0; bi < 2; bi++) ldm4(bl[bi], ldm_addr(cur + 3 * TILEB, wn + bi * 16, kk, lane));
#pragma unroll
            for (int mi = 0; mi < 4; mi++)
#pragma unroll
                for (int j = 0; j < 4; j++) {
                    int bi = j >> 1, s = j & 1;
                    mma16816(acc[mi][j], ah[mi], bh[bi][s], bh[bi][s + 2]);
                    mma16816(acc[mi][j], ah[mi], bl[bi][s], bl[bi][s + 2]);
                    mma16816(acc[mi][j], al[mi], bh[bi][s], bh[bi][s + 2]);
                }
        }
        __syncthreads();
    }

#pragma unroll
    for (int mi = 0; mi < 4; mi++) {
        int r = m0 + wm + mi * 16 + (lane >> 2);
#pragma unroll
        for (int j = 0; j < 4; j++) {
            int cc = n0 + wn + j * 8 + (lane & 3) * 2;
            if (r < NN)
                *(float2*)(C + (size_t)r * HH + cc) = make_float2(acc[mi][j][0], acc[mi][j][1]);
            if (r + 8 < NN)
                *(float2*)(C + (size_t)(r + 8) * HH + cc) = make_float2(acc[mi][j][2], acc[mi][j][3]);
        }
    }
}

// ============== fused GAT layer: score + online softmax + aggregate + LN ==========
// one block per dst node, warp h handles head h. Flash-style online softmax.
__device__ __forceinline__ float score8(float4 x0, float4 r0, float4 e0, float4 t0,
                                        float4 x1, float4 r1, float4 e1, float4 t1) {
    float p = 0.f, v;
    v = x0.x + r0.x + e0.x; v = v > 0.f ? v : NEGS * v; p = fmaf(v, t0.x, p);
    v = x0.y + r0.y + e0.y; v = v > 0.f ? v : NEGS * v; p = fmaf(v, t0.y, p);
    v = x0.z + r0.z + e0.z; v = v > 0.f ? v : NEGS * v; p = fmaf(v, t0.z, p);
    v = x0.w + r0.w + e0.w; v = v > 0.f ? v : NEGS * v; p = fmaf(v, t0.w, p);
    v = x1.x + r1.x + e1.x; v = v > 0.f ? v : NEGS * v; p = fmaf(v, t1.x, p);
    v = x1.y + r1.y + e1.y; v = v > 0.f ? v : NEGS * v; p = fmaf(v, t1.y, p);
    v = x1.z + r1.z + e1.z; v = v > 0.f ? v : NEGS * v; p = fmaf(v, t1.z, p);
    v = x1.w + r1.w + e1.w; v = v > 0.f ? v : NEGS * v; p = fmaf(v, t1.w, p);
#pragma unroll
    for (int o = 16; o; o >>= 1) p += __shfl_xor_sync(0xffffffffu, p, o);
    return p;
}

__device__ __forceinline__ void online_upd(float sc, float4 x0, float4 x1,
                                           float& m, float& s, float4& a0, float4& a1) {
    if (sc > m) {
        float c = __expf(m - sc);          // m init -1e30 -> c = 0 on first edge
        s = fmaf(s, c, 1.f);
        a0.x = fmaf(a0.x, c, x0.x); a0.y = fmaf(a0.y, c, x0.y);
        a0.z = fmaf(a0.z, c, x0.z); a0.w = fmaf(a0.w, c, x0.w);
        a1.x = fmaf(a1.x, c, x1.x); a1.y = fmaf(a1.y, c, x1.y);
        a1.z = fmaf(a1.z, c, x1.z); a1.w = fmaf(a1.w, c, x1.w);
        m = sc;
    } else {
        float p = __expf(sc - m);
        s += p;
        a0.x = fmaf(x0.x, p, a0.x); a0.y = fmaf(x0.y, p, a0.y);
        a0.z = fmaf(x0.z, p, a0.z); a0.w = fmaf(x0.w, p, a0.w);
        a1.x = fmaf(x1.x, p, a1.x); a1.y = fmaf(x1.y, p, a1.y);
        a1.z = fmaf(x1.z, p, a1.z); a1.w = fmaf(x1.w, p, a1.w);
    }
}

__global__ void __launch_bounds__(256) k_gat(const float* __restrict__ edge_attr,
                                             const int* __restrict__ ei,
                                             const float* __restrict__ We_l,
                                             const float* __restrict__ att_l,
                                             const float* __restrict__ bias,
                                             const float* __restrict__ lng,
                                             const float* __restrict__ lnb) {
    __shared__ float sm[8 * 264];
    __shared__ float red[16];
    int n = blockIdx.x;
    int tid = threadIdx.x, lane = tid & 31, h = tid >> 5;

    const float4* xr4 = (const float4*)(g_xr + (size_t)n * HH + h * HD);
    float4 r0 = xr4[lane], r1 = xr4[lane + 32];
    const float4* at4 = (const float4*)(att_l + h * HD);
    float4 t0 = at4[lane], t1 = at4[lane + 32];

    int beg = g_csr_ptr[n], end = g_csr_ptr[n + 1];
    int c0 = h * 64 + lane, c1 = c0 + 32;
    const float4* W4 = (const float4*)We_l;   // [k][512] float4

    float m = -1e30f, s = 0.f;
    float4 a0 = make_float4(0.f, 0.f, 0.f, 0.f), a1 = a0;

    for (int i = beg; i < end; i += 2) {
        int e0 = g_csr_eid[i];
        bool has1 = (i + 1) < end;
        int e1 = has1 ? g_csr_eid[i + 1] : e0;
        int s0 = (e0 < NE) ? ei[e0] : e0 - NE;
        int s1 = (e1 < NE) ? ei[e1] : e1 - NE;
        const float* q0 = (e0 < NE) ? edge_attr + e0 * BOND : g_loop + (e0 - NE) * BOND;
        const float* q1 = (e1 < NE) ? edge_attr + e1 * BOND : g_loop + (e1 - NE) * BOND;

        float4 e00 = make_float4(0.f, 0.f, 0.f, 0.f), e01 = e00, e10 = e00, e11 = e00;
#pragma unroll
        for (int k = 0; k < BOND; k++) {
            float4 w0 = W4[k * (HH / 4) + c0];
            float4 w1 = W4[k * (HH / 4) + c1];
            float qa = __ldg(q0 + k), qb = __ldg(q1 + k);
            e00.x = fmaf(qa, w0.x, e00.x); e00.y = fmaf(qa, w0.y, e00.y);
            e00.z = fmaf(qa, w0.z, e00.z); e00.w = fmaf(qa, w0.w, e00.w);
            e01.x = fmaf(qa, w1.x, e01.x); e01.y = fmaf(qa, w1.y, e01.y);
            e01.z = fmaf(qa, w1.z, e01.z); e01.w = fmaf(qa, w1.w, e01.w);
            e10.x = fmaf(qb, w0.x, e10.x); e10.y = fmaf(qb, w0.y, e10.y);
            e10.z = fmaf(qb, w0.z, e10.z); e10.w = fmaf(qb, w0.w, e10.w);
            e11.x = fmaf(qb, w1.x, e11.x); e11.y = fmaf(qb, w1.y, e11.y);
            e11.z = fmaf(qb, w1.z, e11.z); e11.w = fmaf(qb, w1.w, e11.w);
        }
        const float4* xA = (const float4*)(g_xl + (size_t)s0 * HH + h * HD);
        const float4* xB = (const float4*)(g_xl + (size_t)s1 * HH + h * HD);
        float4 x00 = xA[lane], x01 = xA[lane + 32];
        float4 x10 = xB[lane], x11 = xB[lane + 32];

        float sc0 = score8(x00, r0, e00, t0, x01, r1, e01, t1);
        online_upd(sc0, x00, x01, m, s, a0, a1);
        if (has1) {
            float sc1 = score8(x10, r0, e10, t0, x11, r1, e11, t1);
            online_upd(sc1, x10, x11, m, s, a0, a1);
        }
    }

    // normalized, head-mean folded (1/8)
    float inv = 1.f / (8.f * s);
    float* smrow = sm + h * 264;
    *(float4*)(smrow + 4 * lane) = make_float4(a0.x * inv, a0.y * inv, a0.z * inv, a0.w * inv);
    *(float4*)(smrow + 128 + 4 * lane) = make_float4(a1.x * inv, a1.y * inv, a1.z * inv, a1.w * inv);
    __syncthreads();

    float o = 0.f;
#pragma unroll
    for (int hh2 = 0; hh2 < 8; hh2++) o += sm[hh2 * 264 + tid];
    float v = o + bias[tid] + g_h[n * HD + tid];

    float ss = v, qq = v * v;
#pragma unroll
    for (int of = 16; of; of >>= 1) {
        ss += __shfl_xor_sync(0xffffffffu, ss, of);
        qq += __shfl_xor_sync(0xffffffffu, qq, of);
    }
    if (!lane) { red[h] = ss; red[8 + h] = qq; }
    __syncthreads();
    if (tid == 0) {
        float ts = 0.f, tq = 0.f;
        for (int i = 0; i < 8; i++) { ts += red[i]; tq += red[8 + i]; }
        red[0] = ts; red[8] = tq;
    }
    __syncthreads();
    float mean = red[0] * (1.f / HD);
    float var = red[8] * (1.f / HD) - mean * mean;
    float hn = (v - mean) * rsqrtf(var + LNEPS) * lng[tid] + lnb[tid];
    int idx = n * HD + tid;
    g_h[idx] = hn;
    __nv_bfloat16 hi = __float2bfloat16(hn);
    g_hh[idx] = hi;
    g_hl[idx] = __float2bfloat16(hn - __bfloat162float(hi));
}

// ---------------- readout ----------------
__global__ void k_init_post(float* __restrict__ out) {
    int i = blockIdx.x * 256 + threadIdx.x;
    if (i < NB) { g_gmax[i] = __int_as_float(0xff800000); g_gsum[i] = 0.f; }
    if (i < NB * HD) out[i] = 0.f;
}

__global__ void __launch_bounds__(128) k_gate(const float* __restrict__ g1W, const float* __restrict__ g1b,
                                              const float* __restrict__ g2W, const float* __restrict__ g2b,
                                              const int* __restrict__ bv) {
    __shared__ float hs[HD];
    __shared__ float rs[4];
    int n = blockIdx.x, tid = threadIdx.x;
    hs[tid] = g_h[n * HD + tid];
    hs[tid + 128] = g_h[n * HD + tid + 128];
    __syncthreads();
    float t = g1b[tid];
    for (int d = 0; d < HD; d++) t = fmaf(hs[d], g1W[d * 128 + tid], t);
    t = fmaxf(t, 0.f) * g2W[tid];
#pragma unroll
    for (int o = 16; o; o >>= 1) t += __shfl_xor_sync(0xffffffffu, t, o);
    if (!(tid & 31)) rs[tid >> 5] = t;
    __syncthreads();
    if (tid == 0) {
        float tot = rs[0] + rs[1] + rs[2] + rs[3] + g2b[0];
        g_gate[n] = tot;
        atomicMaxF(&g_gmax[bv[n]], tot);
    }
}

__global__ void k_gate_exp(const int* __restrict__ bv) {
    int i = blockIdx.x * 256 + threadIdx.x;
    if (i >= NN) return;
    int b = bv[i];
    float ge = expf(g_gate[i] - g_gmax[b]);
    g_gate[i] = ge;
    atomicAdd(&g_gsum[b], ge);
}

__global__ void __launch_bounds__(256) k_out(const int* __restrict__ bv, float* __restrict__ out) {
    int n = blockIdx.x, tid = threadIdx.x;
    int b = bv[n];
    float w = g_gate[n] / fmaxf(g_gsum[b], 1e-16f);
    atomicAdd(&out[b * HD + tid], w * g_h[n * HD + tid]);
}

// ---------------- launch ----------------
extern "C" void kernel_launch(void* const* d_in, const int* in_sizes, int n_in,
                              void* d_out, int out_size) {
    const float* x        = (const float*)d_in[0];
    const float* edge_attr= (const float*)d_in[1];
    const float* emb_W    = (const float*)d_in[2];
    const float* emb_b    = (const float*)d_in[3];
    const float* emb_g    = (const float*)d_in[4];
    const float* emb_beta = (const float*)d_in[5];
    const float* Wl       = (const float*)d_in[6];
    const float* Wr       = (const float*)d_in[7];
    const float* We       = (const float*)d_in[8];
    const float* att      = (const float*)d_in[9];
    const float* bias     = (const float*)d_in[10];
    const float* ln_g     = (const float*)d_in[11];
    const float* ln_b     = (const float*)d_in[12];
    const float* g1W      = (const float*)d_in[13];
    const float* g1b      = (const float*)d_in[14];
    const float* g2W      = (const float*)d_in[15];
    const float* g2b      = (const float*)d_in[16];
    const int*   ei       = (const int*)d_in[17];
    const int*   bv       = (const int*)d_in[18];
    float* out = (float*)d_out;

    cudaFuncSetAttribute(k_gemm_mma, cudaFuncAttributeMaxDynamicSharedMemorySize, GEMM_SMEM);

    k_init0<<<(NN * BOND + 255) / 256, 256>>>();
    k_loop_acc<<<(NE + 255) / 256, 256>>>(edge_attr, ei);
    k_loop_fin<<<(NN * BOND + 255) / 256, 256>>>();
    k_csr_count<<<(EAA + 255) / 256, 256>>>(ei);
    k_csr_scan<<<1, 1024>>>();
    k_csr_fill<<<(EAA + 255) / 256, 256>>>(ei);
    k_embed<<<NN, 256>>>(x, emb_W, emb_b, emb_g, emb_beta);

    dim3 ggrid(HH / 128, (NN + 127) / 128, 2);
    for (int l = 0; l < NL; l++) {
        k_w_split<<<dim3(HH / 32, HD / 32), 256>>>(Wl + (size_t)l * HD * HH, Wr + (size_t)l * HD * HH);
        k_gemm_mma<<<ggrid, 256, GEMM_SMEM>>>();
        k_gat<<<NN, 256>>>(edge_attr, ei, We + (size_t)l * BOND * HH,
                           att + (size_t)l * NHEADS * HD,
                           bias + l * HD, ln_g + l * HD, ln_b + l * HD);
    }

    k_init_post<<<(NB * HD + 255) / 256, 256>>>(out);
    k_gate<<<NN, 128>>>(g1W, g1b, g2W, g2b, bv);
    k_gate_exp<<<(NN + 255) / 256, 256>>>(bv);
    k_out<<<NN, 256>>>(bv, out);
}